// round 1
// baseline (speedup 1.0000x reference)
#include <cuda_runtime.h>
#include <math.h>

// Problem constants (shapes fixed by the dataset)
#define NN   50000
#define EE   800000
#define DH   256
#define NL   8

// ---------------- scratch (static device globals; no allocs) ----------------
__device__ float g_x0[NN * DH];
__device__ float g_h[NN * DH];
__device__ float g_agg[NN * DH];
__device__ float g_dis[NN];
__device__ int   g_counts[NN];
__device__ int   g_cursor[NN];
__device__ int   g_rowptr[NN + 1];
__device__ int   g_csr[EE];
__device__ float g_wc[NL * 2 * DH * DH];   // stacked [0.5*W1; 0.5*W2] per layer
__device__ float g_part[2048];
__device__ float g_part2[2048];
__device__ float g_stats[2];

// ---------------- f32x2 helpers ----------------
__device__ __forceinline__ unsigned long long pack_dup(float x) {
    unsigned long long r; unsigned u = __float_as_uint(x);
    asm("mov.b64 %0, {%1, %1};" : "=l"(r) : "r"(u));
    return r;
}
__device__ __forceinline__ float2 unpack2(unsigned long long v) {
    unsigned lo, hi;
    asm("mov.b64 {%0, %1}, %2;" : "=r"(lo), "=r"(hi) : "l"(v));
    return make_float2(__uint_as_float(lo), __uint_as_float(hi));
}
#define FMA2(acc, a, b) asm("fma.rn.f32x2 %0, %1, %2, %0;" : "+l"(acc) : "l"(a), "l"(b))

// ---------------- graph preprocessing ----------------
__global__ void k_init(int n) {
    int i = blockIdx.x * blockDim.x + threadIdx.x;
    if (i < n) { g_counts[i] = 0; g_cursor[i] = 0; }
}

__global__ void k_count(const int* __restrict__ col, int E) {
    int e = blockIdx.x * blockDim.x + threadIdx.x;
    if (e < E) atomicAdd(&g_counts[col[e]], 1);
}

__global__ void k_scan(int n, int E) {
    __shared__ int sh[1024];
    int tid = threadIdx.x;
    int C = (n + 1023) >> 10;
    int base = tid * C;
    int s = 0;
    for (int i = 0; i < C; i++) { int idx = base + i; if (idx < n) s += g_counts[idx]; }
    sh[tid] = s; __syncthreads();
    for (int off = 1; off < 1024; off <<= 1) {
        int v = (tid >= off) ? sh[tid - off] : 0;
        __syncthreads();
        sh[tid] += v;
        __syncthreads();
    }
    int run = (tid > 0) ? sh[tid - 1] : 0;
    for (int i = 0; i < C; i++) {
        int idx = base + i;
        if (idx < n) {
            g_rowptr[idx] = run;
            int c = g_counts[idx];
            run += c;
            g_dis[idx] = rsqrtf((float)(c + 1));   // +1 self-loop
        }
    }
    if (tid == 0) g_rowptr[n] = E;
}

__global__ void k_scatter(const int* __restrict__ row, const int* __restrict__ col, int E) {
    int e = blockIdx.x * blockDim.x + threadIdx.x;
    if (e < E) {
        int c = col[e];
        int p = g_rowptr[c] + atomicAdd(&g_cursor[c], 1);
        g_csr[p] = row[e];
    }
}

__global__ void k_prescale(const float* __restrict__ w1, const float* __restrict__ w2) {
    int idx = blockIdx.x * blockDim.x + threadIdx.x;
    if (idx < NL * 2 * DH * DH) {
        int l = idx >> 17;            // / (512*256)
        int rem = idx & 131071;
        int k = rem >> 8;             // 0..511
        int nn = rem & 255;
        float v = (k < DH) ? w1[(l << 16) + (k << 8) + nn]
                           : w2[(l << 16) + ((k - DH) << 8) + nn];
        g_wc[idx] = 0.5f * v;
    }
}

// ---------------- per-layer sparse aggregation (CSR gather) ----------------
__global__ void k_gather(int n) {
    int w = (blockIdx.x * blockDim.x + threadIdx.x) >> 5;
    int lane = threadIdx.x & 31;
    if (w >= n) return;
    const float4* __restrict__ h4 = (const float4*)g_h;
    float dc = g_dis[w];
    int base = w * 64;
    float4 v0 = h4[base + lane], v1 = h4[base + 32 + lane];
    float4 a0, a1;
    a0.x = dc * v0.x; a0.y = dc * v0.y; a0.z = dc * v0.z; a0.w = dc * v0.w;
    a1.x = dc * v1.x; a1.y = dc * v1.y; a1.z = dc * v1.z; a1.w = dc * v1.w;
    int beg = g_rowptr[w], end = g_rowptr[w + 1];
    int i = beg;
    for (; i + 1 < end; i += 2) {
        int s0 = g_csr[i], s1 = g_csr[i + 1];
        float w0 = g_dis[s0], w1 = g_dis[s1];
        int b0 = s0 * 64, b1 = s1 * 64;
        float4 p0 = h4[b0 + lane], p1 = h4[b0 + 32 + lane];
        float4 q0 = h4[b1 + lane], q1 = h4[b1 + 32 + lane];
        a0.x += w0 * p0.x + w1 * q0.x; a0.y += w0 * p0.y + w1 * q0.y;
        a0.z += w0 * p0.z + w1 * q0.z; a0.w += w0 * p0.w + w1 * q0.w;
        a1.x += w0 * p1.x + w1 * q1.x; a1.y += w0 * p1.y + w1 * q1.y;
        a1.z += w0 * p1.z + w1 * q1.z; a1.w += w0 * p1.w + w1 * q1.w;
    }
    if (i < end) {
        int s0 = g_csr[i];
        float w0 = g_dis[s0];
        int b0 = s0 * 64;
        float4 p0 = h4[b0 + lane], p1 = h4[b0 + 32 + lane];
        a0.x += w0 * p0.x; a0.y += w0 * p0.y; a0.z += w0 * p0.z; a0.w += w0 * p0.w;
        a1.x += w0 * p1.x; a1.y += w0 * p1.y; a1.z += w0 * p1.z; a1.w += w0 * p1.w;
    }
    a0.x *= dc; a0.y *= dc; a0.z *= dc; a0.w *= dc;
    a1.x *= dc; a1.y *= dc; a1.z *= dc; a1.w *= dc;
    float4* __restrict__ o4 = (float4*)g_agg;
    o4[base + lane] = a0;
    o4[base + 32 + lane] = a1;
}

// ---------------- GEMM (128x128 tile, BK=16, 8x8/thread via f32x2) ----------------
// MODE 0: C = relu(x @ lin1_w + b)      -> g_x0 and g_h      (A = Aext, K=128)
// MODE 1: h = c0*(agg+x0) + c1*([agg|x0] @ g_wc[l])          (K=512, B prescaled by 0.5)
// MODE 2: out = relu(h @ lin2_w + b)    -> Cext              (K=256, N=128)
template <int MODE>
__global__ __launch_bounds__(256, 2)
void k_gemm(const float* __restrict__ Aext, const float* __restrict__ Bext,
            const float* __restrict__ bias, float* __restrict__ Cext,
            int M, int K, int ldb, int loff, float c0, float c1)
{
    __shared__ float As[16][128];
    __shared__ float Bs[16][128];
    int tid = threadIdx.x;
    int m0 = blockIdx.x * 128, n0 = blockIdx.y * 128;
    int ty = tid >> 4, tx = tid & 15;

    int ar = tid >> 1;
    int akq = (tid & 1) * 8;
    int am = m0 + ar; if (am > M - 1) am = M - 1;
    int bk = tid >> 4;
    int bnq = (tid & 15) * 8;

    const float* __restrict__ Bp = (MODE == 1) ? &g_wc[loff] : Bext;

    unsigned long long acc[8][4];
#pragma unroll
    for (int i = 0; i < 8; i++)
#pragma unroll
        for (int j = 0; j < 4; j++) acc[i][j] = 0ull;

    for (int k0 = 0; k0 < K; k0 += 16) {
        const float* asrc;
        if (MODE == 0) {
            asrc = Aext + am * 128 + k0 + akq;
        } else if (MODE == 1) {
            int k = k0 + akq;
            asrc = (k < DH) ? &g_agg[am * DH + k] : &g_x0[am * DH + (k - DH)];
        } else {
            asrc = &g_h[am * DH + k0 + akq];
        }
        float4 av0 = *(const float4*)asrc;
        float4 av1 = *(const float4*)(asrc + 4);
        const float* bsrc = Bp + (k0 + bk) * ldb + n0 + bnq;
        float4 bv0 = *(const float4*)bsrc;
        float4 bv1 = *(const float4*)(bsrc + 4);

        __syncthreads();
        As[akq + 0][ar] = av0.x; As[akq + 1][ar] = av0.y;
        As[akq + 2][ar] = av0.z; As[akq + 3][ar] = av0.w;
        As[akq + 4][ar] = av1.x; As[akq + 5][ar] = av1.y;
        As[akq + 6][ar] = av1.z; As[akq + 7][ar] = av1.w;
        *(float4*)&Bs[bk][bnq] = bv0;
        *(float4*)&Bs[bk][bnq + 4] = bv1;
        __syncthreads();

#pragma unroll
        for (int kk = 0; kk < 16; kk++) {
            float4 aA = *(const float4*)&As[kk][ty * 8];
            float4 aB = *(const float4*)&As[kk][ty * 8 + 4];
            ulonglong2 bb0 = *(const ulonglong2*)&Bs[kk][tx * 4];
            ulonglong2 bb1 = *(const ulonglong2*)&Bs[kk][64 + tx * 4];
            unsigned long long ad[8];
            ad[0] = pack_dup(aA.x); ad[1] = pack_dup(aA.y);
            ad[2] = pack_dup(aA.z); ad[3] = pack_dup(aA.w);
            ad[4] = pack_dup(aB.x); ad[5] = pack_dup(aB.y);
            ad[6] = pack_dup(aB.z); ad[7] = pack_dup(aB.w);
#pragma unroll
            for (int i = 0; i < 8; i++) {
                FMA2(acc[i][0], ad[i], bb0.x);
                FMA2(acc[i][1], ad[i], bb0.y);
                FMA2(acc[i][2], ad[i], bb1.x);
                FMA2(acc[i][3], ad[i], bb1.y);
            }
        }
    }

    int nA = n0 + tx * 4;
    int nB = n0 + 64 + tx * 4;
    float4 biasA, biasB;
    if (MODE != 1) {
        biasA = *(const float4*)&bias[nA];
        biasB = *(const float4*)&bias[nB];
    }

#pragma unroll
    for (int i = 0; i < 8; i++) {
        int m = m0 + ty * 8 + i;
        if (m >= M) continue;
        float2 p0 = unpack2(acc[i][0]), p1 = unpack2(acc[i][1]);
        float2 p2 = unpack2(acc[i][2]), p3 = unpack2(acc[i][3]);
        float4 vA = make_float4(p0.x, p0.y, p1.x, p1.y);
        float4 vB = make_float4(p2.x, p2.y, p3.x, p3.y);

        if (MODE == 0) {
            vA.x = fmaxf(vA.x + biasA.x, 0.f); vA.y = fmaxf(vA.y + biasA.y, 0.f);
            vA.z = fmaxf(vA.z + biasA.z, 0.f); vA.w = fmaxf(vA.w + biasA.w, 0.f);
            vB.x = fmaxf(vB.x + biasB.x, 0.f); vB.y = fmaxf(vB.y + biasB.y, 0.f);
            vB.z = fmaxf(vB.z + biasB.z, 0.f); vB.w = fmaxf(vB.w + biasB.w, 0.f);
            int o = m * DH;
            *(float4*)&g_x0[o + nA] = vA; *(float4*)&g_x0[o + nB] = vB;
            *(float4*)&g_h[o + nA] = vA;  *(float4*)&g_h[o + nB] = vB;
        } else if (MODE == 1) {
            int o = m * DH;
            float4 gA = *(const float4*)&g_agg[o + nA];
            float4 gB = *(const float4*)&g_agg[o + nB];
            float4 xA = *(const float4*)&g_x0[o + nA];
            float4 xB = *(const float4*)&g_x0[o + nB];
            vA.x = c0 * (gA.x + xA.x) + c1 * vA.x;
            vA.y = c0 * (gA.y + xA.y) + c1 * vA.y;
            vA.z = c0 * (gA.z + xA.z) + c1 * vA.z;
            vA.w = c0 * (gA.w + xA.w) + c1 * vA.w;
            vB.x = c0 * (gB.x + xB.x) + c1 * vB.x;
            vB.y = c0 * (gB.y + xB.y) + c1 * vB.y;
            vB.z = c0 * (gB.z + xB.z) + c1 * vB.z;
            vB.w = c0 * (gB.w + xB.w) + c1 * vB.w;
            *(float4*)&g_h[o + nA] = vA; *(float4*)&g_h[o + nB] = vB;
        } else {
            vA.x = fmaxf(vA.x + biasA.x, 0.f); vA.y = fmaxf(vA.y + biasA.y, 0.f);
            vA.z = fmaxf(vA.z + biasA.z, 0.f); vA.w = fmaxf(vA.w + biasA.w, 0.f);
            vB.x = fmaxf(vB.x + biasB.x, 0.f); vB.y = fmaxf(vB.y + biasB.y, 0.f);
            vB.z = fmaxf(vB.z + biasB.z, 0.f); vB.w = fmaxf(vB.w + biasB.w, 0.f);
            int o = m * 128;
            *(float4*)&Cext[o + nA] = vA; *(float4*)&Cext[o + nB] = vB;
        }
    }
}

// ---------------- graph layernorm (deterministic two-stage reduce) ----------------
__global__ void k_reduce1(int total4) {
    int tid = blockIdx.x * blockDim.x + threadIdx.x;
    int stride = gridDim.x * blockDim.x;
    const float4* __restrict__ h4 = (const float4*)g_h;
    float s = 0.f, ss = 0.f;
    for (int i = tid; i < total4; i += stride) {
        float4 v = h4[i];
        s += (v.x + v.y) + (v.z + v.w);
        ss += v.x * v.x + v.y * v.y + v.z * v.z + v.w * v.w;
    }
    __shared__ float sa[256], sb[256];
    int t = threadIdx.x;
    sa[t] = s; sb[t] = ss; __syncthreads();
    for (int off = 128; off > 0; off >>= 1) {
        if (t < off) { sa[t] += sa[t + off]; sb[t] += sb[t + off]; }
        __syncthreads();
    }
    if (t == 0) { g_part[blockIdx.x] = sa[0]; g_part2[blockIdx.x] = sb[0]; }
}

__global__ void k_reduce2(int nblocks, float invcnt) {
    __shared__ float sa[1024], sb[1024];
    int t = threadIdx.x;
    float s = 0.f, ss = 0.f;
    for (int i = t; i < nblocks; i += 1024) { s += g_part[i]; ss += g_part2[i]; }
    sa[t] = s; sb[t] = ss; __syncthreads();
    for (int off = 512; off > 0; off >>= 1) {
        if (t < off) { sa[t] += sa[t + off]; sb[t] += sb[t + off]; }
        __syncthreads();
    }
    if (t == 0) {
        float mu = sa[0] * invcnt;
        float var = sb[0] * invcnt - mu * mu;
        var = fmaxf(var, 0.f);
        g_stats[0] = mu;
        g_stats[1] = 1.0f / (sqrtf(var) + 1e-5f);
    }
}

__global__ void k_norm(const float* __restrict__ gamma, const float* __restrict__ beta, int total4) {
    int i = blockIdx.x * blockDim.x + threadIdx.x;
    if (i >= total4) return;
    float mu = g_stats[0], inv = g_stats[1];
    float4 v = ((const float4*)g_h)[i];
    int f = (i * 4) & 255;
    float4 g = *(const float4*)&gamma[f];
    float4 b = *(const float4*)&beta[f];
    v.x = fmaxf(g.x * ((v.x - mu) * inv) + b.x, 0.f);
    v.y = fmaxf(g.y * ((v.y - mu) * inv) + b.y, 0.f);
    v.z = fmaxf(g.z * ((v.z - mu) * inv) + b.z, 0.f);
    v.w = fmaxf(g.w * ((v.w - mu) * inv) + b.w, 0.f);
    ((float4*)g_h)[i] = v;
}

// ---------------- launch ----------------
extern "C" void kernel_launch(void* const* d_in, const int* in_sizes, int n_in,
                              void* d_out, int out_size) {
    const float* x      = (const float*)d_in[0];
    const int*   ei     = (const int*)d_in[1];
    const float* lin1_w = (const float*)d_in[2];
    const float* lin1_b = (const float*)d_in[3];
    const float* w1     = (const float*)d_in[4];
    const float* w2     = (const float*)d_in[5];
    const float* gamma  = (const float*)d_in[6];
    const float* betab  = (const float*)d_in[7];
    const float* lin2_w = (const float*)d_in[8];
    const float* lin2_b = (const float*)d_in[9];
    float* out = (float*)d_out;

    int N = in_sizes[0] / 128;
    int E = in_sizes[1] / 2;
    const int* row = ei;
    const int* col = ei + E;

    int Mt = (N + 127) / 128;
    int total4 = N * (DH / 4);

    k_init<<<(N + 255) / 256, 256>>>(N);
    k_count<<<(E + 255) / 256, 256>>>(col, E);
    k_scan<<<1, 1024>>>(N, E);
    k_scatter<<<(E + 255) / 256, 256>>>(row, col, E);
    k_prescale<<<(NL * 2 * DH * DH + 255) / 256, 256>>>(w1, w2);

    // x0 = relu(x @ lin1_w + b), h = x0
    k_gemm<0><<<dim3(Mt, 2), 256>>>(x, lin1_w, lin1_b, nullptr, N, 128, 256, 0, 0.f, 0.f);

    for (int l = 0; l < NL; l++) {
        float beta_l = logf(1.0f / (float)(l + 1) + 1.0f);
        float c0 = 0.5f * (1.0f - beta_l);   // applied to (agg + x0)
        float c1 = beta_l;                   // weights already scaled by 0.5
        k_gather<<<(N * 32 + 255) / 256, 256>>>(N);
        k_gemm<1><<<dim3(Mt, 2), 256>>>(nullptr, nullptr, nullptr, nullptr,
                                        N, 512, 256, l * 2 * DH * DH, c0, c1);
        k_reduce1<<<2048, 256>>>(total4);
        k_reduce2<<<1, 1024>>>(2048, 1.0f / ((float)N * (float)DH));
        k_norm<<<(total4 + 255) / 256, 256>>>(gamma + l * DH, betab + l * DH, total4);
    }

    // out = relu(h @ lin2_w + b)
    k_gemm<2><<<dim3(Mt, 1), 256>>>(nullptr, lin2_w, lin2_b, out, N, 256, 128, 0, 0.f, 0.f);
}

// round 3
// speedup vs baseline: 1.9322x; 1.9322x over previous
#include <cuda_runtime.h>
#include <cuda_bf16.h>
#include <math.h>
#include <stdint.h>

#define NN 50000
#define EE 800000
#define DH 256
#define NL 8
#define NTILES ((NN + 127) / 128)   // 391
#define NPAD (NTILES * 128)

// ---------------- scratch (static device globals; zero-initialized) ----------------
__device__ float g_h[NN * DH];
__device__ __align__(16) __nv_bfloat16 g_ahh[(size_t)NPAD * 512];  // A hi  [node][k]  k<256 agg, k>=256 x0
__device__ __align__(16) __nv_bfloat16 g_all[(size_t)NPAD * 512];  // A lo
__device__ __align__(16) __nv_bfloat16 g_bhh[(size_t)NL * 512 * 256];  // B' hi [layer][k][n]
__device__ __align__(16) __nv_bfloat16 g_bll[(size_t)NL * 512 * 256];  // B' lo
__device__ float g_dis[NN];
__device__ int   g_counts[NN];
__device__ int   g_cursor[NN];
__device__ int   g_rowptr[NN + 1];
__device__ int   g_csr[EE];
__device__ float g_part[NTILES * 2 + 8];
__device__ float g_part2[NTILES * 2 + 8];
__device__ float g_stats[2];

// ---------------- helpers ----------------
__device__ __forceinline__ uint32_t s2u(const void* p) {
    uint32_t a;
    asm("{ .reg .u64 t; cvta.to.shared.u64 t, %1; cvt.u32.u64 %0, t; }" : "=r"(a) : "l"(p));
    return a;
}
__device__ __forceinline__ void cp16(uint32_t dst, const void* src) {
    asm volatile("cp.async.cg.shared.global [%0], [%1], 16;" :: "r"(dst), "l"(src) : "memory");
}
#define CP_COMMIT() asm volatile("cp.async.commit_group;" ::: "memory")
#define CP_WAIT(n)  asm volatile("cp.async.wait_group %0;" :: "n"(n) : "memory")

#define LDSM4(r0,r1,r2,r3,a) \
    asm volatile("ldmatrix.sync.aligned.m8n8.x4.shared.b16 {%0,%1,%2,%3}, [%4];" \
                 : "=r"(r0),"=r"(r1),"=r"(r2),"=r"(r3) : "r"(a))
#define LDSM4T(r0,r1,r2,r3,a) \
    asm volatile("ldmatrix.sync.aligned.m8n8.x4.trans.shared.b16 {%0,%1,%2,%3}, [%4];" \
                 : "=r"(r0),"=r"(r1),"=r"(r2),"=r"(r3) : "r"(a))
#define MMA_BF16(c,a,b0,b1) \
    asm volatile("mma.sync.aligned.m16n8k16.row.col.f32.bf16.bf16.f32 " \
                 "{%0,%1,%2,%3}, {%4,%5,%6,%7}, {%8,%9}, {%0,%1,%2,%3};" \
                 : "+f"((c)[0]),"+f"((c)[1]),"+f"((c)[2]),"+f"((c)[3]) \
                 : "r"((a)[0]),"r"((a)[1]),"r"((a)[2]),"r"((a)[3]),"r"(b0),"r"(b1))

__device__ __forceinline__ void split_bf16(float v, __nv_bfloat16& h, __nv_bfloat16& l) {
    h = __float2bfloat16_rn(v);
    l = __float2bfloat16_rn(v - __bfloat162float(h));
}

// ---------------- graph preprocessing ----------------
__global__ void k_init(int n) {
    int i = blockIdx.x * blockDim.x + threadIdx.x;
    if (i < n) { g_counts[i] = 0; g_cursor[i] = 0; }
}
__global__ void k_count(const int* __restrict__ col, int E) {
    int e = blockIdx.x * blockDim.x + threadIdx.x;
    if (e < E) atomicAdd(&g_counts[col[e]], 1);
}
__global__ void k_scan(int n, int E) {
    __shared__ int sh[1024];
    int tid = threadIdx.x;
    int C = (n + 1023) >> 10;
    int base = tid * C;
    int s = 0;
    for (int i = 0; i < C; i++) { int idx = base + i; if (idx < n) s += g_counts[idx]; }
    sh[tid] = s; __syncthreads();
    for (int off = 1; off < 1024; off <<= 1) {
        int v = (tid >= off) ? sh[tid - off] : 0;
        __syncthreads();
        sh[tid] += v;
        __syncthreads();
    }
    int run = (tid > 0) ? sh[tid - 1] : 0;
    for (int i = 0; i < C; i++) {
        int idx = base + i;
        if (idx < n) {
            g_rowptr[idx] = run;
            int c = g_counts[idx];
            run += c;
            g_dis[idx] = rsqrtf((float)(c + 1));
        }
    }
    if (tid == 0) g_rowptr[n] = E;
}
__global__ void k_scatter(const int* __restrict__ row, const int* __restrict__ col, int E) {
    int e = blockIdx.x * blockDim.x + threadIdx.x;
    if (e < E) {
        int c = col[e];
        int p = g_rowptr[c] + atomicAdd(&g_cursor[c], 1);
        g_csr[p] = row[e];
    }
}

// ---------------- B' prep: B'[k,n] = 0.5*(beta*W[k,n]) + 0.5*(1-beta)*diag ----------------
__global__ void k_prep_b(const float* __restrict__ w1, const float* __restrict__ w2) {
    int idx = blockIdx.x * blockDim.x + threadIdx.x;
    if (idx >= NL * 512 * 256) return;
    int n = idx & 255;
    int k = (idx >> 8) & 511;
    int l = idx >> 17;
    float beta = logf(1.0f / (float)(l + 1) + 1.0f);
    float v = (k < 256) ? w1[(l << 16) + (k << 8) + n]
                        : w2[(l << 16) + ((k - 256) << 8) + n];
    float val = 0.5f * beta * v;
    if (k == n || k == n + 256) val += 0.5f * (1.0f - beta);
    __nv_bfloat16 h, lo; split_bf16(val, h, lo);
    g_bhh[idx] = h;
    g_bll[idx] = lo;
}

// ---------------- CSR gather -> bf16 hi/lo A rows (k 0..255) ----------------
__global__ void k_gather(int n) {
    int w = (blockIdx.x * blockDim.x + threadIdx.x) >> 5;
    int lane = threadIdx.x & 31;
    if (w >= n) return;
    const float4* __restrict__ h4 = (const float4*)g_h;
    float dc = g_dis[w];
    int base = w * 64;
    float4 v0 = h4[base + lane], v1 = h4[base + 32 + lane];
    float4 a0, a1;
    a0.x = dc * v0.x; a0.y = dc * v0.y; a0.z = dc * v0.z; a0.w = dc * v0.w;
    a1.x = dc * v1.x; a1.y = dc * v1.y; a1.z = dc * v1.z; a1.w = dc * v1.w;
    int beg = g_rowptr[w], end = g_rowptr[w + 1];
    int i = beg;
    for (; i + 1 < end; i += 2) {
        int s0 = g_csr[i], s1 = g_csr[i + 1];
        float w0 = g_dis[s0], w1 = g_dis[s1];
        int b0 = s0 * 64, b1 = s1 * 64;
        float4 p0 = h4[b0 + lane], p1 = h4[b0 + 32 + lane];
        float4 q0 = h4[b1 + lane], q1 = h4[b1 + 32 + lane];
        a0.x += w0 * p0.x + w1 * q0.x; a0.y += w0 * p0.y + w1 * q0.y;
        a0.z += w0 * p0.z + w1 * q0.z; a0.w += w0 * p0.w + w1 * q0.w;
        a1.x += w0 * p1.x + w1 * q1.x; a1.y += w0 * p1.y + w1 * q1.y;
        a1.z += w0 * p1.z + w1 * q1.z; a1.w += w0 * p1.w + w1 * q1.w;
    }
    if (i < end) {
        int s0 = g_csr[i];
        float w0 = g_dis[s0];
        int b0 = s0 * 64;
        float4 p0 = h4[b0 + lane], p1 = h4[b0 + 32 + lane];
        a0.x += w0 * p0.x; a0.y += w0 * p0.y; a0.z += w0 * p0.z; a0.w += w0 * p0.w;
        a1.x += w0 * p1.x; a1.y += w0 * p1.y; a1.z += w0 * p1.z; a1.w += w0 * p1.w;
    }
    a0.x *= dc; a0.y *= dc; a0.z *= dc; a0.w *= dc;
    a1.x *= dc; a1.y *= dc; a1.z *= dc; a1.w *= dc;

    __nv_bfloat16 h_[4], l_[4];
    size_t ro = (size_t)w * 512;
    split_bf16(a0.x, h_[0], l_[0]); split_bf16(a0.y, h_[1], l_[1]);
    split_bf16(a0.z, h_[2], l_[2]); split_bf16(a0.w, h_[3], l_[3]);
    *(uint2*)&g_ahh[ro + lane * 4] = *(uint2*)h_;
    *(uint2*)&g_all[ro + lane * 4] = *(uint2*)l_;
    split_bf16(a1.x, h_[0], l_[0]); split_bf16(a1.y, h_[1], l_[1]);
    split_bf16(a1.z, h_[2], l_[2]); split_bf16(a1.w, h_[3], l_[3]);
    *(uint2*)&g_ahh[ro + 128 + lane * 4] = *(uint2*)h_;
    *(uint2*)&g_all[ro + 128 + lane * 4] = *(uint2*)l_;
}

// ---------------- bf16 3-pass tensor GEMM: h = [agg|x0] @ B' + fused LN partials ----------------
// CTA: 128(M) x 128(N), K = 512 in 8 chunks of 64. 256 threads = 8 warps (4 m x 2 n).
// smem per stage: Ah(16K) Al(16K) Bh(16K) Bl(16K) = 64KB; 2 stages = 128KB.
__global__ __launch_bounds__(256, 1) void k_mma(int layer, int nvalid) {
    extern __shared__ char smem[];
    uint32_t sb = s2u(smem);
    const int tid = threadIdx.x, lane = tid & 31, wid = tid >> 5;
    const int T = blockIdx.x, nh = blockIdx.y;

    const __nv_bfloat16* __restrict__ Agh = g_ahh + (size_t)T * 128 * 512;
    const __nv_bfloat16* __restrict__ Agl = g_all + (size_t)T * 128 * 512;
    const __nv_bfloat16* __restrict__ Bgh = g_bhh + (size_t)layer * 512 * 256 + nh * 128;
    const __nv_bfloat16* __restrict__ Bgl = g_bll + (size_t)layer * 512 * 256 + nh * 128;

    // per-thread load indices
    const int am = tid >> 1;                 // A: 128 rows x 8 chunks -> e = tid + i*256
    // (recomputed in loop)

    // ---- load chunk c into stage st ----
    auto load_chunk = [&](int c, int st) {
        uint32_t s0 = sb + st * 65536;
#pragma unroll
        for (int i = 0; i < 4; i++) {
            int e = tid + i * 256;
            int m = e >> 3, kc = e & 7;
            uint32_t da = m * 128 + ((kc ^ (m & 7)) << 4);
            const __nv_bfloat16* sa = Agh + (size_t)m * 512 + c * 64 + kc * 8;
            const __nv_bfloat16* sl = Agl + (size_t)m * 512 + c * 64 + kc * 8;
            cp16(s0 + da, sa);
            cp16(s0 + 16384 + da, sl);
            int k = e >> 4, nc = e & 15;
            uint32_t db = k * 256 + ((nc ^ (k & 7)) << 4);
            const __nv_bfloat16* sbh = Bgh + (size_t)(c * 64 + k) * 256 + nc * 8;
            const __nv_bfloat16* sbl = Bgl + (size_t)(c * 64 + k) * 256 + nc * 8;
            cp16(s0 + 32768 + db, sbh);
            cp16(s0 + 49152 + db, sbl);
        }
        CP_COMMIT();
    };
    (void)am;

    float c[2][8][4];
#pragma unroll
    for (int i = 0; i < 2; i++)
#pragma unroll
        for (int j = 0; j < 8; j++)
#pragma unroll
            for (int q = 0; q < 4; q++) c[i][j][q] = 0.f;

    const int wm = (wid & 3) * 32, wn = (wid >> 2) * 64;

    load_chunk(0, 0);
    for (int ch = 0; ch < 8; ch++) {
        if (ch < 7) { load_chunk(ch + 1, (ch + 1) & 1); CP_WAIT(1); }
        else        { CP_WAIT(0); }
        __syncthreads();
        uint32_t s0 = sb + (ch & 1) * 65536;
        uint32_t sah = s0, sal = s0 + 16384, sbh = s0 + 32768, sbl = s0 + 49152;

#pragma unroll
        for (int kq = 0; kq < 4; kq++) {            // k16 steps within the 64-chunk
            uint32_t ah[2][4], al[2][4], bh[4][4], bl[4][4];
#pragma unroll
            for (int mi = 0; mi < 2; mi++) {
                int m = wm + mi * 16 + (lane & 15);
                int kc = kq * 2 + (lane >> 4);
                uint32_t ad = m * 128 + ((kc ^ (m & 7)) << 4);
                LDSM4(ah[mi][0], ah[mi][1], ah[mi][2], ah[mi][3], sah + ad);
                LDSM4(al[mi][0], al[mi][1], al[mi][2], al[mi][3], sal + ad);
            }
#pragma unroll
            for (int nj = 0; nj < 4; nj++) {
                int kr = kq * 16 + (lane & 15);
                int nc = (wn >> 3) + nj * 2 + (lane >> 4);
                uint32_t bd = kr * 256 + ((nc ^ (kr & 7)) << 4);
                LDSM4T(bh[nj][0], bh[nj][1], bh[nj][2], bh[nj][3], sbh + bd);
                LDSM4T(bl[nj][0], bl[nj][1], bl[nj][2], bl[nj][3], sbl + bd);
            }
#pragma unroll
            for (int mi = 0; mi < 2; mi++)
#pragma unroll
                for (int nt = 0; nt < 8; nt++) {
                    int nj = nt >> 1, pq = (nt & 1) * 2;
                    MMA_BF16(c[mi][nt], ah[mi], bh[nj][pq], bh[nj][pq + 1]);
                    MMA_BF16(c[mi][nt], ah[mi], bl[nj][pq], bl[nj][pq + 1]);
                    MMA_BF16(c[mi][nt], al[mi], bh[nj][pq], bh[nj][pq + 1]);
                }
        }
        __syncthreads();
    }

    // ---- epilogue: write h, accumulate LN partials ----
    float s = 0.f, ss = 0.f;
    int rbase = T * 128 + wm + (lane >> 2);
    int cbase = nh * 128 + wn + (lane & 3) * 2;
#pragma unroll
    for (int mi = 0; mi < 2; mi++) {
        int r0 = rbase + mi * 16;
        int r1 = r0 + 8;
        bool v0 = r0 < nvalid, v1 = r1 < nvalid;
#pragma unroll
        for (int nt = 0; nt < 8; nt++) {
            int col = cbase + nt * 8;
            if (v0) {
                float2 p = make_float2(c[mi][nt][0], c[mi][nt][1]);
                *(float2*)&g_h[(size_t)r0 * DH + col] = p;
                s += p.x + p.y; ss += p.x * p.x + p.y * p.y;
            }
            if (v1) {
                float2 p = make_float2(c[mi][nt][2], c[mi][nt][3]);
                *(float2*)&g_h[(size_t)r1 * DH + col] = p;
                s += p.x + p.y; ss += p.x * p.x + p.y * p.y;
            }
        }
    }
    __syncthreads();
    float* red = (float*)smem;
    red[tid] = s; red[256 + tid] = ss;
    __syncthreads();
    for (int o = 128; o > 0; o >>= 1) {
        if (tid < o) { red[tid] += red[tid + o]; red[256 + tid] += red[256 + tid + o]; }
        __syncthreads();
    }
    if (tid == 0) {
        int slot = nh * gridDim.x + T;
        g_part[slot] = red[0];
        g_part2[slot] = red[256];
    }
}

// ---------------- dense f32x2 GEMM for lin1 / lin2 ----------------
__device__ __forceinline__ unsigned long long pack_dup(float x) {
    unsigned long long r; unsigned u = __float_as_uint(x);
    asm("mov.b64 %0, {%1, %1};" : "=l"(r) : "r"(u));
    return r;
}
__device__ __forceinline__ float2 unpack2(unsigned long long v) {
    unsigned lo, hi;
    asm("mov.b64 {%0, %1}, %2;" : "=r"(lo), "=r"(hi) : "l"(v));
    return make_float2(__uint_as_float(lo), __uint_as_float(hi));
}
#define FMA2(acc, a, b) asm("fma.rn.f32x2 %0, %1, %2, %0;" : "+l"(acc) : "l"(a), "l"(b))

// MODE 0: x0 = relu(x @ lin1_w + b) -> g_h + bf16 hi/lo A rows (k 256..511)
// MODE 2: out = relu(g_h @ lin2_w + b) -> Cext
template <int MODE>
__global__ __launch_bounds__(256, 2)
void k_gemm(const float* __restrict__ Aext, const float* __restrict__ Bext,
            const float* __restrict__ bias, float* __restrict__ Cext,
            int M, int K, int ldb)
{
    __shared__ float As[16][128];
    __shared__ float Bs[16][128];
    int tid = threadIdx.x;
    int m0 = blockIdx.x * 128, n0 = blockIdx.y * 128;
    int ty = tid >> 4, tx = tid & 15;

    int ar = tid >> 1;
    int akq = (tid & 1) * 8;
    int am = m0 + ar; if (am > M - 1) am = M - 1;
    int bk = tid >> 4;
    int bnq = (tid & 15) * 8;

    unsigned long long acc[8][4];
#pragma unroll
    for (int i = 0; i < 8; i++)
#pragma unroll
        for (int j = 0; j < 4; j++) acc[i][j] = 0ull;

    for (int k0 = 0; k0 < K; k0 += 16) {
        const float* asrc;
        if (MODE == 0) asrc = Aext + am * 128 + k0 + akq;
        else           asrc = &g_h[(size_t)am * DH + k0 + akq];
        float4 av0 = *(const float4*)asrc;
        float4 av1 = *(const float4*)(asrc + 4);
        const float* bsrc = Bext + (k0 + bk) * ldb + n0 + bnq;
        float4 bv0 = *(const float4*)bsrc;
        float4 bv1 = *(const float4*)(bsrc + 4);

        __syncthreads();
        As[akq + 0][ar] = av0.x; As[akq + 1][ar] = av0.y;
        As[akq + 2][ar] = av0.z; As[akq + 3][ar] = av0.w;
        As[akq + 4][ar] = av1.x; As[akq + 5][ar] = av1.y;
        As[akq + 6][ar] = av1.z; As[akq + 7][ar] = av1.w;
        *(float4*)&Bs[bk][bnq] = bv0;
        *(float4*)&Bs[bk][bnq + 4] = bv1;
        __syncthreads();

#pragma unroll
        for (int kk = 0; kk < 16; kk++) {
            float4 aA = *(const float4*)&As[kk][ty * 8];
            float4 aB = *(const float4*)&As[kk][ty * 8 + 4];
            ulonglong2 bb0 = *(const ulonglong2*)&Bs[kk][tx * 4];
            ulonglong2 bb1 = *(const ulonglong2*)&Bs[kk][64 + tx * 4];
            unsigned long long ad[8];
            ad[0] = pack_dup(aA.x); ad[1] = pack_dup(aA.y);
            ad[2] = pack_dup(aA.z); ad[3] = pack_dup(aA.w);
            ad[4] = pack_dup(aB.x); ad[5] = pack_dup(aB.y);
            ad[6] = pack_dup(aB.z); ad[7] = pack_dup(aB.w);
#pragma unroll
            for (int i = 0; i < 8; i++) {
                FMA2(acc[i][0], ad[i], bb0.x);
                FMA2(acc[i][1], ad[i], bb0.y);
                FMA2(acc[i][2], ad[i], bb1.x);
                FMA2(acc[i][3], ad[i], bb1.y);
            }
        }
    }

    int nA = n0 + tx * 4;
    int nB = n0 + 64 + tx * 4;
    float4 biasA = *(const float4*)&bias[nA];
    float4 biasB = *(const float4*)&bias[nB];

#pragma unroll
    for (int i = 0; i < 8; i++) {
        int m = m0 + ty * 8 + i;
        if (m >= M) continue;
        float2 p0 = unpack2(acc[i][0]), p1 = unpack2(acc[i][1]);
        float2 p2 = unpack2(acc[i][2]), p3 = unpack2(acc[i][3]);
        float4 vA = make_float4(fmaxf(p0.x + biasA.x, 0.f), fmaxf(p0.y + biasA.y, 0.f),
                                fmaxf(p1.x + biasA.z, 0.f), fmaxf(p1.y + biasA.w, 0.f));
        float4 vB = make_float4(fmaxf(p2.x + biasB.x, 0.f), fmaxf(p2.y + biasB.y, 0.f),
                                fmaxf(p3.x + biasB.z, 0.f), fmaxf(p3.y + biasB.w, 0.f));

        if (MODE == 0) {
            size_t o = (size_t)m * DH;
            *(float4*)&g_h[o + nA] = vA;
            *(float4*)&g_h[o + nB] = vB;
            size_t ro = (size_t)m * 512 + 256;
            __nv_bfloat16 h_[4], l_[4];
            split_bf16(vA.x, h_[0], l_[0]); split_bf16(vA.y, h_[1], l_[1]);
            split_bf16(vA.z, h_[2], l_[2]); split_bf16(vA.w, h_[3], l_[3]);
            *(uint2*)&g_ahh[ro + nA] = *(uint2*)h_;
            *(uint2*)&g_all[ro + nA] = *(uint2*)l_;
            split_bf16(vB.x, h_[0], l_[0]); split_bf16(vB.y, h_[1], l_[1]);
            split_bf16(vB.z, h_[2], l_[2]); split_bf16(vB.w, h_[3], l_[3]);
            *(uint2*)&g_ahh[ro + nB] = *(uint2*)h_;
            *(uint2*)&g_all[ro + nB] = *(uint2*)l_;
        } else {
            size_t o = (size_t)m * 128;
            *(float4*)&Cext[o + nA] = vA;
            *(float4*)&Cext[o + nB] = vB;
        }
    }
}

// ---------------- layernorm finalize + normalize ----------------
__global__ void k_reduce2(int nblocks, float invcnt) {
    __shared__ float sa[1024], sb[1024];
    int t = threadIdx.x;
    float s = 0.f, ss = 0.f;
    for (int i = t; i < nblocks; i += 1024) { s += g_part[i]; ss += g_part2[i]; }
    sa[t] = s; sb[t] = ss; __syncthreads();
    for (int off = 512; off > 0; off >>= 1) {
        if (t < off) { sa[t] += sa[t + off]; sb[t] += sb[t + off]; }
        __syncthreads();
    }
    if (t == 0) {
        float mu = sa[0] * invcnt;
        float var = sb[0] * invcnt - mu * mu;
        var = fmaxf(var, 0.f);
        g_stats[0] = mu;
        g_stats[1] = 1.0f / (sqrtf(var) + 1e-5f);
    }
}

__global__ void k_norm(const float* __restrict__ gamma, const float* __restrict__ beta, int total4) {
    int i = blockIdx.x * blockDim.x + threadIdx.x;
    if (i >= total4) return;
    float mu = g_stats[0], inv = g_stats[1];
    float4 v = ((const float4*)g_h)[i];
    int f = (i * 4) & 255;
    float4 g = *(const float4*)&gamma[f];
    float4 b = *(const float4*)&beta[f];
    v.x = fmaxf(g.x * ((v.x - mu) * inv) + b.x, 0.f);
    v.y = fmaxf(g.y * ((v.y - mu) * inv) + b.y, 0.f);
    v.z = fmaxf(g.z * ((v.z - mu) * inv) + b.z, 0.f);
    v.w = fmaxf(g.w * ((v.w - mu) * inv) + b.w, 0.f);
    ((float4*)g_h)[i] = v;
}

// ---------------- launch ----------------
extern "C" void kernel_launch(void* const* d_in, const int* in_sizes, int n_in,
                              void* d_out, int out_size) {
    const float* x      = (const float*)d_in[0];
    const int*   ei     = (const int*)d_in[1];
    const float* lin1_w = (const float*)d_in[2];
    const float* lin1_b = (const float*)d_in[3];
    const float* w1     = (const float*)d_in[4];
    const float* w2     = (const float*)d_in[5];
    const float* gamma  = (const float*)d_in[6];
    const float* betab  = (const float*)d_in[7];
    const float* lin2_w = (const float*)d_in[8];
    const float* lin2_b = (const float*)d_in[9];
    float* out = (float*)d_out;

    int N = in_sizes[0] / 128;
    int E = in_sizes[1] / 2;
    const int* row = ei;
    const int* col = ei + E;

    int Mt = (N + 127) / 128;
    int total4 = N * (DH / 4);

    static int smem_set = 0;
    if (!smem_set) {
        cudaFuncSetAttribute(k_mma, cudaFuncAttributeMaxDynamicSharedMemorySize, 131072);
        smem_set = 1;
    }

    k_init<<<(N + 255) / 256, 256>>>(N);
    k_count<<<(E + 255) / 256, 256>>>(col, E);
    k_scan<<<1, 1024>>>(N, E);
    k_scatter<<<(E + 255) / 256, 256>>>(row, col, E);
    k_prep_b<<<(NL * 512 * 256 + 255) / 256, 256>>>(w1, w2);

    // x0 = relu(x @ lin1_w + b)
    k_gemm<0><<<dim3(Mt, 2), 256>>>(x, lin1_w, lin1_b, nullptr, N, 128, 256);

    for (int l = 0; l < NL; l++) {
        k_gather<<<(N * 32 + 255) / 256, 256>>>(N);
        k_mma<<<dim3(Mt, 2), 256, 131072>>>(l, N);
        k_reduce2<<<1, 1024>>>(Mt * 2, 1.0f / ((float)N * (float)DH));
        k_norm<<<(total4 + 255) / 256, 256>>>(gamma + l * DH, betab + l * DH, total4);
    }

    k_gemm<2><<<dim3(Mt, 1), 256>>>(nullptr, lin2_w, lin2_b, out, N, 256, 128);
}